// round 1
// baseline (speedup 1.0000x reference)
#include <cuda_runtime.h>
#include <math.h>

#define HH 256
#define WW 256
#define HW (HH*WW)

// ---------------- scratch (static device globals; no allocs) ----------------
__device__ float g_t1[64 * HW];
__device__ float g_t2[64 * HW];
__device__ float g_off[216 * HW];     // raw offset-branch conv4 output
__device__ float g_samp[576 * HW];    // gathered, mask-weighted samples
__device__ float g_cat[128 * HW];     // concat(fp, fn) for fusion conv

// ---------------- conv3x3, pad 1, stride 1 ----------------
// Block: 256 threads = 16(tx) x 16(ty). Tile: 32 wide x 16 high (2 px/thread).
// 16 output channels per block (blockIdx.z). Cin processed in chunks of 8.
template<bool LRELU>
__global__ void conv3x3_kernel(const float* __restrict__ in,
                               const float* __restrict__ w,
                               const float* __restrict__ bias,
                               float* __restrict__ out,
                               int Cin, int Cout) {
    __shared__ float s_in[8][18][48];   // row stride 48 (==16 mod 32): conflict-free halo reads
    __shared__ float s_w[16][8][9];

    const int tid = threadIdx.x;
    const int tx = tid & 15, ty = tid >> 4;
    const int x0 = blockIdx.x * 32, y0 = blockIdx.y * 16;
    const int ocb = blockIdx.z * 16;

    float acc0[16], acc1[16];
#pragma unroll
    for (int i = 0; i < 16; i++) { acc0[i] = 0.f; acc1[i] = 0.f; }

    for (int c0 = 0; c0 < Cin; c0 += 8) {
        // load 8-channel input tile (18 rows x 34 cols used)
        for (int i = tid; i < 8 * 18 * 34; i += 256) {
            int c = i / (18 * 34);
            int rem = i % (18 * 34);
            int r = rem / 34, col = rem % 34;
            int gy = y0 + r - 1, gx = x0 + col - 1;
            float v = 0.f;
            if (gy >= 0 && gy < HH && gx >= 0 && gx < WW)
                v = in[(c0 + c) * HW + gy * WW + gx];
            s_in[c][r][col] = v;
        }
        // load weights for this oc block / cin chunk
        for (int i = tid; i < 16 * 8 * 9; i += 256) {
            int oc = i / 72, c = (i % 72) / 9, k = i % 9;
            float v = 0.f;
            if (ocb + oc < Cout) v = w[((ocb + oc) * Cin + (c0 + c)) * 9 + k];
            s_w[oc][c][k] = v;
        }
        __syncthreads();

#pragma unroll
        for (int c = 0; c < 8; c++) {
            float v0[9], v1[9];
#pragma unroll
            for (int t = 0; t < 9; t++) {
                int ky = t / 3, kx = t % 3;
                v0[t] = s_in[c][ty + ky][tx + kx];
                v1[t] = s_in[c][ty + ky][tx + 16 + kx];
            }
#pragma unroll
            for (int oc = 0; oc < 16; oc++) {
#pragma unroll
                for (int t = 0; t < 9; t++) {
                    float wv = s_w[oc][c][t];
                    acc0[oc] += v0[t] * wv;
                    acc1[oc] += v1[t] * wv;
                }
            }
        }
        __syncthreads();
    }

    const int y = y0 + ty;
#pragma unroll
    for (int oc = 0; oc < 16; oc++) {
        if (ocb + oc >= Cout) break;
        float bv = bias[ocb + oc];
        float r0 = acc0[oc] + bv;
        float r1 = acc1[oc] + bv;
        if (LRELU) {
            r0 = (r0 >= 0.f) ? r0 : 0.1f * r0;
            r1 = (r1 >= 0.f) ? r1 : 0.1f * r1;
        }
        out[(ocb + oc) * HW + y * WW + x0 + tx]      = r0;
        out[(ocb + oc) * HW + y * WW + x0 + tx + 16] = r1;
    }
}

// ---------------- deformable gather ----------------
// One thread per (g,k,px). Writes mask-weighted bilinear samples for 8 channels
// into g_samp with row index (g*8+c)*9+k  (== flattened dcn_w cin*9+k ordering).
__global__ void gather_kernel(const float* __restrict__ feat,
                              const float* __restrict__ offraw,
                              const float* __restrict__ flow) {
    const int px = blockIdx.x * 256 + threadIdx.x;
    const int gk = blockIdx.y;                // 0..71
    const int g = gk / 9, k = gk % 9;
    const int y = px >> 8, x = px & 255;

    float offy = 10.f * tanhf(offraw[(gk * 2 + 0) * HW + px]) + flow[HW + px]; // + flow ch1
    float offx = 10.f * tanhf(offraw[(gk * 2 + 1) * HW + px]) + flow[px];      // + flow ch0
    float m = 1.f / (1.f + expf(-offraw[(144 + gk) * HW + px]));

    float py = (float)y + (float)(k / 3 - 1) + offy;
    float pxx = (float)x + (float)(k % 3 - 1) + offx;
    float y0f = floorf(py), x0f = floorf(pxx);
    float ly = py - y0f, lx = pxx - x0f;
    int yi0 = (int)y0f, xi0 = (int)x0f;
    int yi1 = yi0 + 1, xi1 = xi0 + 1;

    float vy0 = (yi0 >= 0 && yi0 < HH) ? 1.f : 0.f;
    float vy1 = (yi1 >= 0 && yi1 < HH) ? 1.f : 0.f;
    float vx0 = (xi0 >= 0 && xi0 < WW) ? 1.f : 0.f;
    float vx1 = (xi1 >= 0 && xi1 < WW) ? 1.f : 0.f;

    int yc0 = min(max(yi0, 0), HH - 1);
    int yc1 = min(max(yi1, 0), HH - 1);
    int xc0 = min(max(xi0, 0), WW - 1);
    int xc1 = min(max(xi1, 0), WW - 1);

    float w00 = (1.f - ly) * (1.f - lx) * vy0 * vx0 * m;
    float w01 = (1.f - ly) * lx         * vy0 * vx1 * m;
    float w10 = ly         * (1.f - lx) * vy1 * vx0 * m;
    float w11 = ly         * lx         * vy1 * vx1 * m;

    int i00 = yc0 * WW + xc0;
    int i01 = yc0 * WW + xc1;
    int i10 = yc1 * WW + xc0;
    int i11 = yc1 * WW + xc1;

    const float* f = feat + g * 8 * HW;
#pragma unroll
    for (int c = 0; c < 8; c++) {
        const float* fc = f + c * HW;
        float v = w00 * fc[i00] + w01 * fc[i01] + w10 * fc[i10] + w11 * fc[i11];
        g_samp[((g * 8 + c) * 9 + k) * HW + px] = v;
    }
}

// ---------------- dcn einsum as GEMM: out[64][HW] = W[64][576] * samp[576][HW] + b ---------
// Block: 256 threads, 512 px, 16 oc (blockIdx.y).
__global__ void dcn_gemm_kernel(const float* __restrict__ w,
                                const float* __restrict__ bias,
                                float* __restrict__ out) {
    __shared__ float s_s[8][512];
    __shared__ float s_w[8][16];
    const int tid = threadIdx.x;
    const int pxb = blockIdx.x * 512;
    const int ocb = blockIdx.y * 16;

    float acc0[16], acc1[16];
#pragma unroll
    for (int i = 0; i < 16; i++) { acc0[i] = 0.f; acc1[i] = 0.f; }

    for (int c0 = 0; c0 < 576; c0 += 8) {
        for (int i = tid; i < 8 * 512; i += 256) {
            int c = i >> 9, j = i & 511;
            s_s[c][j] = g_samp[(c0 + c) * HW + pxb + j];
        }
        if (tid < 128) {
            int c = tid >> 4, oc = tid & 15;
            s_w[c][oc] = w[(ocb + oc) * 576 + c0 + c];
        }
        __syncthreads();
#pragma unroll
        for (int c = 0; c < 8; c++) {
            float v0 = s_s[c][tid];
            float v1 = s_s[c][tid + 256];
#pragma unroll
            for (int oc = 0; oc < 16; oc++) {
                float wv = s_w[c][oc];
                acc0[oc] += v0 * wv;
                acc1[oc] += v1 * wv;
            }
        }
        __syncthreads();
    }
#pragma unroll
    for (int oc = 0; oc < 16; oc++) {
        float bv = bias[ocb + oc];
        out[(ocb + oc) * HW + pxb + tid]       = acc0[oc] + bv;
        out[(ocb + oc) * HW + pxb + tid + 256] = acc1[oc] + bv;
    }
}

// ---------------- host launch ----------------
static void run_branch(const float* feat, const float* extra, const float* flow,
                       const float* w0, const float* b0,
                       const float* w1, const float* b1,
                       const float* w2, const float* b2,
                       const float* w3, const float* b3,
                       const float* dw, const float* db,
                       float* t1, float* t2, float* off, float* branch_out) {
    dim3 blk(256);
    dim3 g64(WW / 32, HH / 16, 64 / 16);
    dim3 g216(WW / 32, HH / 16, (216 + 15) / 16);

    conv3x3_kernel<true ><<<g64,  blk>>>(extra, w0, b0, t1, 128, 64);
    conv3x3_kernel<true ><<<g64,  blk>>>(t1,    w1, b1, t2,  64, 64);
    conv3x3_kernel<true ><<<g64,  blk>>>(t2,    w2, b2, t1,  64, 64);
    conv3x3_kernel<false><<<g216, blk>>>(t1,    w3, b3, off, 64, 216);

    gather_kernel<<<dim3(HW / 256, 72), blk>>>(feat, off, flow);

    dcn_gemm_kernel<<<dim3(HW / 512, 4), blk>>>(dw, db, branch_out);
}

extern "C" void kernel_launch(void* const* d_in, const int* in_sizes, int n_in,
                              void* d_out, int out_size) {
    const float* feat_prev  = (const float*)d_in[0];
    const float* feat_next  = (const float*)d_in[1];
    const float* extra_prev = (const float*)d_in[2];
    const float* extra_next = (const float*)d_in[3];
    const float* flow_prev  = (const float*)d_in[4];
    const float* flow_next  = (const float*)d_in[5];
    // off1: w0 b0 w1 b1 w2 b2 w3 b3 at 6..13 ; off2 at 14..21
    const float* dcn1_w = (const float*)d_in[22];
    const float* dcn1_b = (const float*)d_in[23];
    const float* dcn2_w = (const float*)d_in[24];
    const float* dcn2_b = (const float*)d_in[25];
    const float* fus_w  = (const float*)d_in[26];
    const float* fus_b  = (const float*)d_in[27];

    float *t1, *t2, *off, *cat;
    cudaGetSymbolAddress((void**)&t1,  g_t1);
    cudaGetSymbolAddress((void**)&t2,  g_t2);
    cudaGetSymbolAddress((void**)&off, g_off);
    cudaGetSymbolAddress((void**)&cat, g_cat);

    // branch prev -> cat[0:64]
    run_branch(feat_prev, extra_prev, flow_prev,
               (const float*)d_in[6],  (const float*)d_in[7],
               (const float*)d_in[8],  (const float*)d_in[9],
               (const float*)d_in[10], (const float*)d_in[11],
               (const float*)d_in[12], (const float*)d_in[13],
               dcn1_w, dcn1_b, t1, t2, off, cat);

    // branch next -> cat[64:128]
    run_branch(feat_next, extra_next, flow_next,
               (const float*)d_in[14], (const float*)d_in[15],
               (const float*)d_in[16], (const float*)d_in[17],
               (const float*)d_in[18], (const float*)d_in[19],
               (const float*)d_in[20], (const float*)d_in[21],
               dcn2_w, dcn2_b, t1, t2, off, cat + 64 * HW);

    // fusion conv: cat(128) -> out(64)
    dim3 blk(256);
    dim3 g64(WW / 32, HH / 16, 64 / 16);
    conv3x3_kernel<false><<<g64, blk>>>(cat, fus_w, fus_b, (float*)d_out, 128, 64);
}

// round 2
// speedup vs baseline: 1.3745x; 1.3745x over previous
#include <cuda_runtime.h>
#include <math.h>

#define HH 256
#define WW 256
#define HW (HH*WW)

// ---------------- scratch (static device globals; no allocs) ----------------
__device__ float g_t1[64 * HW];
__device__ float g_t2[64 * HW];
__device__ float g_off[216 * HW];     // raw offset-branch conv4 output
__device__ float g_cat[128 * HW];     // concat(fp, fn) for fusion conv

typedef unsigned long long ull;

// packed f32x2 helpers (sm_100+ PTX)
__device__ __forceinline__ ull pk2(float v) {
    ull r; asm("mov.b64 %0, {%1, %1};" : "=l"(r) : "f"(v)); return r;
}
__device__ __forceinline__ ull ffma2(ull a, ull b, ull c) {
    ull r; asm("fma.rn.f32x2 %0, %1, %2, %3;" : "=l"(r) : "l"(a), "l"(b), "l"(c)); return r;
}
__device__ __forceinline__ void unpk2(ull v, float& lo, float& hi) {
    asm("mov.b64 {%0, %1}, %2;" : "=f"(lo), "=f"(hi) : "l"(v));
}

// ---------------- conv3x3, pad 1, stride 1 (FFMA2 over oc pairs) ----------------
// Block: 256 threads = 16(tx) x 16(ty). Tile: 64 wide (4 px/thread) x 16 high.
// 16 output channels per block (8 f32x2 pairs). Cin in chunks of 8.
template<bool LRELU>
__global__ __launch_bounds__(256, 2)
void conv3x3_kernel(const float* __restrict__ in,
                    const float* __restrict__ w,
                    const float* __restrict__ bias,
                    float* __restrict__ out,
                    int Cin, int Cout) {
    __shared__ __align__(16) float s_in[8][18][67];
    __shared__ __align__(16) float s_w[8][9][16];   // [c][tap][oc] — oc pairs contiguous

    const int tid = threadIdx.x;
    const int tx = tid & 15, ty = tid >> 4;
    const int x0 = blockIdx.x * 64, y0 = blockIdx.y * 16;
    const int ocb = blockIdx.z * 16;

    ull acc[8][4];   // [oc-pair][px] ; each holds (oc=2p, oc=2p+1)
#pragma unroll
    for (int p = 0; p < 8; p++)
#pragma unroll
        for (int q = 0; q < 4; q++) acc[p][q] = 0ULL;

    for (int c0 = 0; c0 < Cin; c0 += 8) {
        // input tile: 8ch x 18 rows x 66 cols
        for (int i = tid; i < 8 * 18 * 66; i += 256) {
            int c = i / (18 * 66);
            int rem = i % (18 * 66);
            int r = rem / 66, col = rem % 66;
            int gy = y0 + r - 1, gx = x0 + col - 1;
            float v = 0.f;
            if (gy >= 0 && gy < HH && gx >= 0 && gx < WW)
                v = in[(c0 + c) * HW + gy * WW + gx];
            s_in[c][r][col] = v;
        }
        // weights
        for (int i = tid; i < 8 * 9 * 16; i += 256) {
            int oc = i & 15, t = (i >> 4) % 9, c = i / 144;
            float v = 0.f;
            if (ocb + oc < Cout) v = w[((ocb + oc) * Cin + (c0 + c)) * 9 + t];
            s_w[c][t][oc] = v;
        }
        __syncthreads();

#pragma unroll
        for (int c = 0; c < 8; c++) {
#pragma unroll
            for (int ky = 0; ky < 3; ky++) {
                ull vin[6];
#pragma unroll
                for (int j = 0; j < 6; j++)
                    vin[j] = pk2(s_in[c][ty + ky][4 * tx + j]);
#pragma unroll
                for (int kx = 0; kx < 3; kx++) {
#pragma unroll
                    for (int p = 0; p < 8; p++) {
                        ull wp = *reinterpret_cast<const ull*>(&s_w[c][ky * 3 + kx][2 * p]);
                        acc[p][0] = ffma2(vin[0 + kx], wp, acc[p][0]);
                        acc[p][1] = ffma2(vin[1 + kx], wp, acc[p][1]);
                        acc[p][2] = ffma2(vin[2 + kx], wp, acc[p][2]);
                        acc[p][3] = ffma2(vin[3 + kx], wp, acc[p][3]);
                    }
                }
            }
        }
        __syncthreads();
    }

    const int y = y0 + ty;
    const int xb = x0 + 4 * tx;
#pragma unroll
    for (int p = 0; p < 8; p++) {
        float lo[4], hi[4];
#pragma unroll
        for (int q = 0; q < 4; q++) unpk2(acc[p][q], lo[q], hi[q]);
        int oc0 = ocb + 2 * p, oc1 = oc0 + 1;
        if (oc0 < Cout) {
            float bv = bias[oc0];
            float4 o;
            o.x = lo[0] + bv; o.y = lo[1] + bv; o.z = lo[2] + bv; o.w = lo[3] + bv;
            if (LRELU) {
                o.x = o.x >= 0.f ? o.x : 0.1f * o.x;
                o.y = o.y >= 0.f ? o.y : 0.1f * o.y;
                o.z = o.z >= 0.f ? o.z : 0.1f * o.z;
                o.w = o.w >= 0.f ? o.w : 0.1f * o.w;
            }
            *reinterpret_cast<float4*>(&out[oc0 * HW + y * WW + xb]) = o;
        }
        if (oc1 < Cout) {
            float bv = bias[oc1];
            float4 o;
            o.x = hi[0] + bv; o.y = hi[1] + bv; o.z = hi[2] + bv; o.w = hi[3] + bv;
            if (LRELU) {
                o.x = o.x >= 0.f ? o.x : 0.1f * o.x;
                o.y = o.y >= 0.f ? o.y : 0.1f * o.y;
                o.z = o.z >= 0.f ? o.z : 0.1f * o.z;
                o.w = o.w >= 0.f ? o.w : 0.1f * o.w;
            }
            *reinterpret_cast<float4*>(&out[oc1 * HW + y * WW + xb]) = o;
        }
    }
}

// ---------------- fused deformable gather + grouped GEMM ----------------
// out[oc][px] = sum_{g,c,k} w[oc][g*72+c*9+k] * bilinear_sample(feat[g*8+c], off[g,k], mask[g,k]) + b
// Block: 256 threads, 512 px (thread owns px tid and tid+256), 32 oc (blockIdx.y half).
// Accums packed f32x2 over oc pairs; weights staged per-g in smem (LDS.64 broadcast).
__global__ __launch_bounds__(256, 2)
void dcn_fused_kernel(const float* __restrict__ feat,
                      const float* __restrict__ offraw,
                      const float* __restrict__ flow,
                      const float* __restrict__ w,
                      const float* __restrict__ bias,
                      float* __restrict__ out) {
    __shared__ __align__(16) float s_w[72][32];   // [c*9+k][oc]

    const int tid = threadIdx.x;
    const int px0 = blockIdx.x * 512;
    const int ocb = blockIdx.y * 32;
    const int pxA = px0 + tid;
    const int pxB = pxA + 256;
    const int yA = pxA >> 8, xA = pxA & 255;
    const int yB = pxB >> 8, xB = pxB & 255;

    const float flAy = flow[HW + pxA], flAx = flow[pxA];
    const float flBy = flow[HW + pxB], flBx = flow[pxB];

    ull acc[16][2];   // [oc-pair][pxA/pxB]
#pragma unroll
    for (int p = 0; p < 16; p++) { acc[p][0] = 0ULL; acc[p][1] = 0ULL; }

    for (int g = 0; g < 8; g++) {
        __syncthreads();
        for (int i = tid; i < 72 * 32; i += 256) {
            int oc = i & 31, ck = i >> 5;
            s_w[ck][oc] = w[(ocb + oc) * 576 + g * 72 + ck];
        }
        __syncthreads();

        const float* fg = feat + g * 8 * HW;

#pragma unroll
        for (int k = 0; k < 9; k++) {
            const int gk = g * 9 + k;
            const float dky = (float)(k / 3 - 1);
            const float dkx = (float)(k % 3 - 1);

            // ---- pixel A bilinear setup ----
            float oyA = 10.f * tanhf(offraw[(gk * 2 + 0) * HW + pxA]) + flAy;
            float oxA = 10.f * tanhf(offraw[(gk * 2 + 1) * HW + pxA]) + flAx;
            float mA = 1.f / (1.f + expf(-offraw[(144 + gk) * HW + pxA]));
            float pyA = (float)yA + dky + oyA;
            float pxxA = (float)xA + dkx + oxA;
            float y0fA = floorf(pyA), x0fA = floorf(pxxA);
            float lyA = pyA - y0fA, lxA = pxxA - x0fA;
            int yi0A = (int)y0fA, xi0A = (int)x0fA;
            int yi1A = yi0A + 1, xi1A = xi0A + 1;
            float vy0A = (yi0A >= 0 && yi0A < HH) ? 1.f : 0.f;
            float vy1A = (yi1A >= 0 && yi1A < HH) ? 1.f : 0.f;
            float vx0A = (xi0A >= 0 && xi0A < WW) ? 1.f : 0.f;
            float vx1A = (xi1A >= 0 && xi1A < WW) ? 1.f : 0.f;
            int yc0A = min(max(yi0A, 0), HH - 1), yc1A = min(max(yi1A, 0), HH - 1);
            int xc0A = min(max(xi0A, 0), WW - 1), xc1A = min(max(xi1A, 0), WW - 1);
            float wA00 = (1.f - lyA) * (1.f - lxA) * vy0A * vx0A * mA;
            float wA01 = (1.f - lyA) * lxA * vy0A * vx1A * mA;
            float wA10 = lyA * (1.f - lxA) * vy1A * vx0A * mA;
            float wA11 = lyA * lxA * vy1A * vx1A * mA;
            int iA00 = yc0A * WW + xc0A, iA01 = yc0A * WW + xc1A;
            int iA10 = yc1A * WW + xc0A, iA11 = yc1A * WW + xc1A;

            // ---- pixel B bilinear setup ----
            float oyB = 10.f * tanhf(offraw[(gk * 2 + 0) * HW + pxB]) + flBy;
            float oxB = 10.f * tanhf(offraw[(gk * 2 + 1) * HW + pxB]) + flBx;
            float mB = 1.f / (1.f + expf(-offraw[(144 + gk) * HW + pxB]));
            float pyB = (float)yB + dky + oyB;
            float pxxB = (float)xB + dkx + oxB;
            float y0fB = floorf(pyB), x0fB = floorf(pxxB);
            float lyB = pyB - y0fB, lxB = pxxB - x0fB;
            int yi0B = (int)y0fB, xi0B = (int)x0fB;
            int yi1B = yi0B + 1, xi1B = xi0B + 1;
            float vy0B = (yi0B >= 0 && yi0B < HH) ? 1.f : 0.f;
            float vy1B = (yi1B >= 0 && yi1B < HH) ? 1.f : 0.f;
            float vx0B = (xi0B >= 0 && xi0B < WW) ? 1.f : 0.f;
            float vx1B = (xi1B >= 0 && xi1B < WW) ? 1.f : 0.f;
            int yc0B = min(max(yi0B, 0), HH - 1), yc1B = min(max(yi1B, 0), HH - 1);
            int xc0B = min(max(xi0B, 0), WW - 1), xc1B = min(max(xi1B, 0), WW - 1);
            float wB00 = (1.f - lyB) * (1.f - lxB) * vy0B * vx0B * mB;
            float wB01 = (1.f - lyB) * lxB * vy0B * vx1B * mB;
            float wB10 = lyB * (1.f - lxB) * vy1B * vx0B * mB;
            float wB11 = lyB * lxB * vy1B * vx1B * mB;
            int iB00 = yc0B * WW + xc0B, iB01 = yc0B * WW + xc1B;
            int iB10 = yc1B * WW + xc0B, iB11 = yc1B * WW + xc1B;

#pragma unroll
            for (int c = 0; c < 8; c++) {
                const float* fc = fg + c * HW;
                float vA = wA00 * fc[iA00] + wA01 * fc[iA01] + wA10 * fc[iA10] + wA11 * fc[iA11];
                float vB = wB00 * fc[iB00] + wB01 * fc[iB01] + wB10 * fc[iB10] + wB11 * fc[iB11];
                ull sA = pk2(vA), sB = pk2(vB);
                const int row = c * 9 + k;
#pragma unroll
                for (int p = 0; p < 16; p++) {
                    ull wp = *reinterpret_cast<const ull*>(&s_w[row][2 * p]);
                    acc[p][0] = ffma2(sA, wp, acc[p][0]);
                    acc[p][1] = ffma2(sB, wp, acc[p][1]);
                }
            }
        }
    }

#pragma unroll
    for (int p = 0; p < 16; p++) {
        int oc0 = ocb + 2 * p, oc1 = oc0 + 1;
        float a0, a1, b0, b1;
        unpk2(acc[p][0], a0, a1);
        unpk2(acc[p][1], b0, b1);
        float bv0 = bias[oc0], bv1 = bias[oc1];
        out[oc0 * HW + pxA] = a0 + bv0;
        out[oc1 * HW + pxA] = a1 + bv1;
        out[oc0 * HW + pxB] = b0 + bv0;
        out[oc1 * HW + pxB] = b1 + bv1;
    }
}

// ---------------- host launch ----------------
static void run_branch(const float* feat, const float* extra, const float* flow,
                       const float* w0, const float* b0,
                       const float* w1, const float* b1,
                       const float* w2, const float* b2,
                       const float* w3, const float* b3,
                       const float* dw, const float* db,
                       float* t1, float* t2, float* off, float* branch_out) {
    dim3 blk(256);
    dim3 g64(WW / 64, HH / 16, 64 / 16);
    dim3 g216(WW / 64, HH / 16, (216 + 15) / 16);

    conv3x3_kernel<true ><<<g64,  blk>>>(extra, w0, b0, t1, 128, 64);
    conv3x3_kernel<true ><<<g64,  blk>>>(t1,    w1, b1, t2,  64, 64);
    conv3x3_kernel<true ><<<g64,  blk>>>(t2,    w2, b2, t1,  64, 64);
    conv3x3_kernel<false><<<g216, blk>>>(t1,    w3, b3, off, 64, 216);

    dcn_fused_kernel<<<dim3(HW / 512, 2), blk>>>(feat, off, flow, dw, db, branch_out);
}

extern "C" void kernel_launch(void* const* d_in, const int* in_sizes, int n_in,
                              void* d_out, int out_size) {
    const float* feat_prev  = (const float*)d_in[0];
    const float* feat_next  = (const float*)d_in[1];
    const float* extra_prev = (const float*)d_in[2];
    const float* extra_next = (const float*)d_in[3];
    const float* flow_prev  = (const float*)d_in[4];
    const float* flow_next  = (const float*)d_in[5];
    const float* dcn1_w = (const float*)d_in[22];
    const float* dcn1_b = (const float*)d_in[23];
    const float* dcn2_w = (const float*)d_in[24];
    const float* dcn2_b = (const float*)d_in[25];
    const float* fus_w  = (const float*)d_in[26];
    const float* fus_b  = (const float*)d_in[27];

    float *t1, *t2, *off, *cat;
    cudaGetSymbolAddress((void**)&t1,  g_t1);
    cudaGetSymbolAddress((void**)&t2,  g_t2);
    cudaGetSymbolAddress((void**)&off, g_off);
    cudaGetSymbolAddress((void**)&cat, g_cat);

    run_branch(feat_prev, extra_prev, flow_prev,
               (const float*)d_in[6],  (const float*)d_in[7],
               (const float*)d_in[8],  (const float*)d_in[9],
               (const float*)d_in[10], (const float*)d_in[11],
               (const float*)d_in[12], (const float*)d_in[13],
               dcn1_w, dcn1_b, t1, t2, off, cat);

    run_branch(feat_next, extra_next, flow_next,
               (const float*)d_in[14], (const float*)d_in[15],
               (const float*)d_in[16], (const float*)d_in[17],
               (const float*)d_in[18], (const float*)d_in[19],
               (const float*)d_in[20], (const float*)d_in[21],
               dcn2_w, dcn2_b, t1, t2, off, cat + 64 * HW);

    dim3 blk(256);
    dim3 g64(WW / 64, HH / 16, 64 / 16);
    conv3x3_kernel<false><<<g64, blk>>>(cat, fus_w, fus_b, (float*)d_out, 128, 64);
}